// round 8
// baseline (speedup 1.0000x reference)
#include <cuda_runtime.h>
#include <cuda_bf16.h>
#include <mma.h>
#include <math.h>
#include <stdint.h>

using namespace nvcuda;

#define T_TOK 2048
#define DHID  1024
#define FINT  1408
#define NEXP  8

// ---------------- device scratch (static: no allocations allowed) ----------
__device__ int            g_count[NEXP];
__device__ int            g_tok[NEXP * T_TOK];
__device__ float          g_wt [NEXP * T_TOK];
__device__ unsigned char  g_kslot[NEXP * T_TOK];

__device__ __nv_bfloat16  g_xh[(size_t)NEXP * T_TOK * DHID];
__device__ __nv_bfloat16  g_xl[(size_t)NEXP * T_TOK * DHID];
__device__ __nv_bfloat16  g_wgh[(size_t)NEXP * DHID * FINT];
__device__ __nv_bfloat16  g_wgl[(size_t)NEXP * DHID * FINT];
__device__ __nv_bfloat16  g_wuh[(size_t)NEXP * DHID * FINT];
__device__ __nv_bfloat16  g_wul[(size_t)NEXP * DHID * FINT];
__device__ __nv_bfloat16  g_wdh[(size_t)NEXP * FINT * DHID];
__device__ __nv_bfloat16  g_wdl[(size_t)NEXP * FINT * DHID];
__device__ __nv_bfloat16  g_hh[(size_t)NEXP * T_TOK * FINT];
__device__ __nv_bfloat16  g_hl[(size_t)NEXP * T_TOK * FINT];
__device__ float          g_y[(size_t)T_TOK * 2 * DHID];

// ---------------- helpers ----------------------------------------------------
__device__ __forceinline__ uint32_t smem_u32(const void* p) {
    uint32_t a;
    asm("{ .reg .u64 t; cvta.to.shared.u64 t, %1; cvt.u32.u64 %0, t; }" : "=r"(a) : "l"(p));
    return a;
}
#define CP16(dst, src)  asm volatile("cp.async.cg.shared.global [%0], [%1], 16;" :: "r"(dst), "l"(src))
#define CP_COMMIT()     asm volatile("cp.async.commit_group;" ::: "memory")
#define CP_WAIT1()      asm volatile("cp.async.wait_group 1;" ::: "memory")
#define CP_WAIT0()      asm volatile("cp.async.wait_group 0;" ::: "memory")

// ---------------- routing ---------------------------------------------------
__global__ void zero_counts_kernel() {
    if (threadIdx.x < NEXP) g_count[threadIdx.x] = 0;
}

__global__ void router_kernel(const float* __restrict__ x,
                              const float* __restrict__ rw) {
    int warp = (blockIdx.x * blockDim.x + threadIdx.x) >> 5;
    int lane = threadIdx.x & 31;
    if (warp >= T_TOK) return;
    const float* xt = x + (size_t)warp * DHID;

    float logit[NEXP];
#pragma unroll
    for (int e = 0; e < NEXP; e++) {
        const float* w = rw + (size_t)e * DHID;
        float s = 0.f;
        for (int i = lane; i < DHID; i += 32) s += xt[i] * w[i];
#pragma unroll
        for (int o = 16; o > 0; o >>= 1) s += __shfl_xor_sync(0xffffffffu, s, o);
        logit[e] = s;
    }
    if (lane == 0) {
        float m = logit[0];
#pragma unroll
        for (int e = 1; e < NEXP; e++) m = fmaxf(m, logit[e]);
        float p[NEXP];
#pragma unroll
        for (int e = 0; e < NEXP; e++) p[e] = expf(logit[e] - m);
        int i1 = 0; float v1 = p[0];
#pragma unroll
        for (int e = 1; e < NEXP; e++) if (p[e] > v1) { v1 = p[e]; i1 = e; }
        int i2 = -1; float v2 = -1.f;
#pragma unroll
        for (int e = 0; e < NEXP; e++) {
            if (e == i1) continue;
            if (p[e] > v2) { v2 = p[e]; i2 = e; }
        }
        float inv = 1.f / (v1 + v2);
        int pos1 = atomicAdd(&g_count[i1], 1);
        g_tok[i1 * T_TOK + pos1] = warp;  g_wt[i1 * T_TOK + pos1] = v1 * inv;  g_kslot[i1 * T_TOK + pos1] = 0;
        int pos2 = atomicAdd(&g_count[i2], 1);
        g_tok[i2 * T_TOK + pos2] = warp;  g_wt[i2 * T_TOK + pos2] = v2 * inv;  g_kslot[i2 * T_TOK + pos2] = 1;
    }
}

__global__ void gather_x_kernel(const float* __restrict__ x) {
    int s = blockIdx.x, e = blockIdx.y;
    if (s >= g_count[e]) return;
    int t = g_tok[e * T_TOK + s];
    const float* src = x + (size_t)t * DHID;
    size_t dst = ((size_t)e * T_TOK + s) * DHID;
    for (int i = threadIdx.x; i < DHID; i += 128) {
        float v = src[i];
        __nv_bfloat16 hi = __float2bfloat16(v);
        __nv_bfloat16 lo = __float2bfloat16(v - __bfloat162float(hi));
        g_xh[dst + i] = hi;
        g_xl[dst + i] = lo;
    }
}

// fused split: blockIdx.y selects {wg, wu, wd}; dest chosen in device code
__global__ void __launch_bounds__(256) split_kernel(const float* __restrict__ wg,
                                                    const float* __restrict__ wu,
                                                    const float* __restrict__ wd) {
    int which = blockIdx.y;
    const float* src = (which == 0) ? wg : (which == 1) ? wu : wd;
    __nv_bfloat16* dh = (which == 0) ? g_wgh : (which == 1) ? g_wuh : g_wdh;
    __nv_bfloat16* dl = (which == 0) ? g_wgl : (which == 1) ? g_wul : g_wdl;
    size_t i = ((size_t)blockIdx.x * 256 + threadIdx.x) * 8;
    float4 v0 = *(const float4*)(src + i);
    float4 v1 = *(const float4*)(src + i + 4);
    __nv_bfloat16 h[8], l[8];
    const float* vv = &v0.x;
#pragma unroll
    for (int j = 0; j < 4; j++) {
        h[j] = __float2bfloat16(vv[j]);
        l[j] = __float2bfloat16(vv[j] - __bfloat162float(h[j]));
    }
    const float* ww = &v1.x;
#pragma unroll
    for (int j = 0; j < 4; j++) {
        h[4 + j] = __float2bfloat16(ww[j]);
        l[4 + j] = __float2bfloat16(ww[j] - __bfloat162float(h[4 + j]));
    }
    *(uint4*)(dh + i) = *(uint4*)h;
    *(uint4*)(dl + i) = *(uint4*)l;
}

// ---------------- gate+up WMMA GEMM (cp.async double-buffered) -------------
// Block tile: 128m x 64n, two B matrices. 8 warps = 4m x 2n, warp tile 32x32.
//   Ah[2][128][40] @0      (20480)
//   Al[2][128][40] @20480  (20480)
//   Bh[2][2][32][72] @40960 (18432)
//   Bl[2][2][32][72] @59392 (18432)   total 77824
#define GU_AH 0
#define GU_AL 20480
#define GU_BH 40960
#define GU_BL 59392
#define GU_ABUF 10240
#define GU_BBUF 9216
#define GU_SMEM 77824

__global__ void __launch_bounds__(256) gu_wmma_kernel() {
    int e   = blockIdx.z;
    int cnt = g_count[e];
    int m0  = blockIdx.y * 128;
    if (m0 >= cnt) return;
    int n0  = blockIdx.x * 64;

    extern __shared__ char dsm[];
    uint32_t sb = smem_u32(dsm);

    int tid = threadIdx.x, wid = tid >> 5, lane = tid & 31;
    int wm = wid & 3, wn = wid >> 2;

    size_t aBase = ((size_t)e * T_TOK + m0) * DHID;
    size_t wBase = (size_t)e * DHID * FINT + n0;
    const __nv_bfloat16* Wh[2] = { g_wgh + wBase, g_wuh + wBase };
    const __nv_bfloat16* Wl[2] = { g_wgl + wBase, g_wul + wBase };

    int ar = tid >> 1, ac = tid & 1;            // A: 128 rows x 2 32B chunks
    int bmat = tid >> 7, brem = tid & 127;      // B: 2 mats x 16 rows x 8 chunks
    int bk = brem >> 3, bc = brem & 7;

    wmma::fragment<wmma::accumulator, 16, 16, 16, float> c[2][2][2];
#pragma unroll
    for (int mat = 0; mat < 2; mat++)
#pragma unroll
        for (int mf = 0; mf < 2; mf++)
#pragma unroll
            for (int nf = 0; nf < 2; nf++)
                wmma::fill_fragment(c[mat][mf][nf], 0.0f);

#define GU_LOAD(t, b) do {                                                        \
    int k0 = (t) << 5;                                                            \
    uint32_t aO = sb + (b) * GU_ABUF + ar * 80 + ac * 32;                         \
    size_t aS = aBase + (size_t)ar * DHID + k0 + ac * 16;                         \
    CP16(GU_AH + aO,      g_xh + aS);                                             \
    CP16(GU_AH + aO + 16, g_xh + aS + 8);                                         \
    CP16(GU_AL + aO,      g_xl + aS);                                             \
    CP16(GU_AL + aO + 16, g_xl + aS + 8);                                         \
    uint32_t bO = sb + (b) * GU_BBUF + bmat * 4608 + bk * 144 + bc * 16;          \
    size_t bS = (size_t)(k0 + bk) * FINT + bc * 8;                                \
    CP16(GU_BH + bO,        Wh[bmat] + bS);                                       \
    CP16(GU_BH + bO + 2304, Wh[bmat] + bS + 16 * FINT);                           \
    CP16(GU_BL + bO,        Wl[bmat] + bS);                                       \
    CP16(GU_BL + bO + 2304, Wl[bmat] + bS + 16 * FINT);                           \
    CP_COMMIT();                                                                  \
} while (0)

    GU_LOAD(0, 0);
    const int NT = DHID / 32;   // 32
    for (int t = 0; t < NT; t++) {
        int b = t & 1;
        if (t + 1 < NT) { GU_LOAD(t + 1, (t + 1) & 1); CP_WAIT1(); }
        else           { CP_WAIT0(); }
        __syncthreads();

        const __nv_bfloat16* Ah = (const __nv_bfloat16*)(dsm + GU_AH + b * GU_ABUF);
        const __nv_bfloat16* Al = (const __nv_bfloat16*)(dsm + GU_AL + b * GU_ABUF);
        const __nv_bfloat16* Bh = (const __nv_bfloat16*)(dsm + GU_BH + b * GU_BBUF);
        const __nv_bfloat16* Bl = (const __nv_bfloat16*)(dsm + GU_BL + b * GU_BBUF);

#pragma unroll
        for (int kk16 = 0; kk16 < 32; kk16 += 16) {
            wmma::fragment<wmma::matrix_a, 16, 16, 16, __nv_bfloat16, wmma::row_major> ah[2], al[2];
#pragma unroll
            for (int mf = 0; mf < 2; mf++) {
                wmma::load_matrix_sync(ah[mf], Ah + (wm * 32 + mf * 16) * 40 + kk16, 40);
                wmma::load_matrix_sync(al[mf], Al + (wm * 32 + mf * 16) * 40 + kk16, 40);
            }
#pragma unroll
            for (int mat = 0; mat < 2; mat++) {
#pragma unroll
                for (int nf = 0; nf < 2; nf++) {
                    wmma::fragment<wmma::matrix_b, 16, 16, 16, __nv_bfloat16, wmma::row_major> bh, bl;
                    wmma::load_matrix_sync(bh, Bh + mat * 2304 + kk16 * 72 + wn * 32 + nf * 16, 72);
                    wmma::load_matrix_sync(bl, Bl + mat * 2304 + kk16 * 72 + wn * 32 + nf * 16, 72);
#pragma unroll
                    for (int mf = 0; mf < 2; mf++) {
                        wmma::mma_sync(c[mat][mf][nf], ah[mf], bh, c[mat][mf][nf]);
                        wmma::mma_sync(c[mat][mf][nf], ah[mf], bl, c[mat][mf][nf]);
                        wmma::mma_sync(c[mat][mf][nf], al[mf], bh, c[mat][mf][nf]);
                    }
                }
            }
        }
        __syncthreads();
    }
#undef GU_LOAD

    // ---- fused SwiGLU epilogue (scratch aliases load buffers; all reads done) ----
    float* buf = (float*)dsm + wid * 1152;    // 32 x 36 floats per warp
    int grow = m0 + wm * 32 + lane;
    bool ok = grow < cnt;
    size_t hbase = ((size_t)e * T_TOK + grow) * FINT + n0 + wn * 32;

#pragma unroll
    for (int mf = 0; mf < 2; mf++)
#pragma unroll
        for (int nf = 0; nf < 2; nf++)
            wmma::store_matrix_sync(&buf[mf * 16 * 36 + nf * 16], c[0][mf][nf], 36, wmma::mem_row_major);
    __syncwarp();
    float gv[32];
#pragma unroll
    for (int j = 0; j < 32; j++) gv[j] = buf[lane * 36 + j];
    __syncwarp();
#pragma unroll
    for (int mf = 0; mf < 2; mf++)
#pragma unroll
        for (int nf = 0; nf < 2; nf++)
            wmma::store_matrix_sync(&buf[mf * 16 * 36 + nf * 16], c[1][mf][nf], 36, wmma::mem_row_major);
    __syncwarp();
    if (ok) {
#pragma unroll
        for (int j = 0; j < 32; j += 2) {
            float u0 = buf[lane * 36 + j];
            float u1 = buf[lane * 36 + j + 1];
            float g0 = gv[j], g1 = gv[j + 1];
            float h0 = g0 / (1.f + expf(-g0)) * u0;
            float h1 = g1 / (1.f + expf(-g1)) * u1;
            __nv_bfloat16 h0h = __float2bfloat16(h0);
            __nv_bfloat16 h1h = __float2bfloat16(h1);
            __nv_bfloat162 vh; vh.x = h0h; vh.y = h1h;
            __nv_bfloat162 vl;
            vl.x = __float2bfloat16(h0 - __bfloat162float(h0h));
            vl.y = __float2bfloat16(h1 - __bfloat162float(h1h));
            *(__nv_bfloat162*)&g_hh[hbase + j] = vh;
            *(__nv_bfloat162*)&g_hl[hbase + j] = vl;
        }
    }
}

// ---------------- down WMMA GEMM (cp.async double-buffered) ----------------
// Block tile 128m x 128n; 8 warps = 4m x 2n; warp tile 32 x 64.
//   Ah[2][128][40] @0      (20480)
//   Al[2][128][40] @20480  (20480)
//   Bh[2][32][136] @40960  (17408)
//   Bl[2][32][136] @58368  (17408)   total 75776
#define DW_AH 0
#define DW_AL 20480
#define DW_BH 40960
#define DW_BL 58368
#define DW_ABUF 10240
#define DW_BBUF 8704
#define DW_SMEM 75776

__global__ void __launch_bounds__(256) down_wmma_kernel() {
    int e   = blockIdx.z;
    int cnt = g_count[e];
    int m0  = blockIdx.y * 128;
    if (m0 >= cnt) return;
    int n0  = blockIdx.x * 128;

    extern __shared__ char dsm[];
    uint32_t sb = smem_u32(dsm);

    int tid = threadIdx.x, wid = tid >> 5, lane = tid & 31;
    int wm = wid & 3, wn = wid >> 2;

    size_t aBase = ((size_t)e * T_TOK + m0) * FINT;
    size_t wBase = (size_t)e * FINT * DHID + n0;
    const __nv_bfloat16* Wh = g_wdh + wBase;
    const __nv_bfloat16* Wl = g_wdl + wBase;

    int ar = tid >> 1, ac = tid & 1;
    int bk = tid >> 4, bc = tid & 15;

    wmma::fragment<wmma::accumulator, 16, 16, 16, float> c[2][4];
#pragma unroll
    for (int mf = 0; mf < 2; mf++)
#pragma unroll
        for (int nf = 0; nf < 4; nf++)
            wmma::fill_fragment(c[mf][nf], 0.0f);

#define DW_LOAD(t, b) do {                                                        \
    int k0 = (t) << 5;                                                            \
    uint32_t aO = sb + (b) * DW_ABUF + ar * 80 + ac * 32;                         \
    size_t aS = aBase + (size_t)ar * FINT + k0 + ac * 16;                         \
    CP16(DW_AH + aO,      g_hh + aS);                                             \
    CP16(DW_AH + aO + 16, g_hh + aS + 8);                                         \
    CP16(DW_AL + aO,      g_hl + aS);                                             \
    CP16(DW_AL + aO + 16, g_hl + aS + 8);                                         \
    uint32_t bO = sb + (b) * DW_BBUF + bk * 272 + bc * 16;                        \
    size_t bS = (size_t)(k0 + bk) * DHID + bc * 8;                                \
    CP16(DW_BH + bO,        Wh + bS);                                             \
    CP16(DW_BH + bO + 4352, Wh + bS + 16 * DHID);                                 \
    CP16(DW_BL + bO,        Wl + bS);                                             \
    CP16(DW_BL + bO + 4352, Wl + bS + 16 * DHID);                                 \
    CP_COMMIT();                                                                  \
} while (0)

    DW_LOAD(0, 0);
    const int NT = FINT / 32;   // 44
    for (int t = 0; t < NT; t++) {
        int b = t & 1;
        if (t + 1 < NT) { DW_LOAD(t + 1, (t + 1) & 1); CP_WAIT1(); }
        else           { CP_WAIT0(); }
        __syncthreads();

        const __nv_bfloat16* Ah = (const __nv_bfloat16*)(dsm + DW_AH + b * DW_ABUF);
        const __nv_bfloat16* Al = (const __nv_bfloat16*)(dsm + DW_AL + b * DW_ABUF);
        const __nv_bfloat16* Bh = (const __nv_bfloat16*)(dsm + DW_BH + b * DW_BBUF);
        const __nv_bfloat16* Bl = (const __nv_bfloat16*)(dsm + DW_BL + b * DW_BBUF);

#pragma unroll
        for (int kk16 = 0; kk16 < 32; kk16 += 16) {
            wmma::fragment<wmma::matrix_a, 16, 16, 16, __nv_bfloat16, wmma::row_major> ah[2], al[2];
#pragma unroll
            for (int mf = 0; mf < 2; mf++) {
                wmma::load_matrix_sync(ah[mf], Ah + (wm * 32 + mf * 16) * 40 + kk16, 40);
                wmma::load_matrix_sync(al[mf], Al + (wm * 32 + mf * 16) * 40 + kk16, 40);
            }
#pragma unroll
            for (int nf = 0; nf < 4; nf++) {
                wmma::fragment<wmma::matrix_b, 16, 16, 16, __nv_bfloat16, wmma::row_major> bh, bl;
                wmma::load_matrix_sync(bh, Bh + kk16 * 136 + wn * 64 + nf * 16, 136);
                wmma::load_matrix_sync(bl, Bl + kk16 * 136 + wn * 64 + nf * 16, 136);
#pragma unroll
                for (int mf = 0; mf < 2; mf++) {
                    wmma::mma_sync(c[mf][nf], ah[mf], bh, c[mf][nf]);
                    wmma::mma_sync(c[mf][nf], ah[mf], bl, c[mf][nf]);
                    wmma::mma_sync(c[mf][nf], al[mf], bh, c[mf][nf]);
                }
            }
        }
        __syncthreads();
    }
#undef DW_LOAD

    // ---- scaled scatter epilogue ----
    float* buf = (float*)dsm + wid * 1152;
    int grow = m0 + wm * 32 + lane;
    bool ok = grow < cnt;
    int   tok = 0, ks = 0;
    float w = 0.f;
    if (ok) {
        tok = g_tok[e * T_TOK + grow];
        w   = g_wt [e * T_TOK + grow];
        ks  = g_kslot[e * T_TOK + grow];
    }
    size_t ybase = ((size_t)tok * 2 + ks) * DHID + n0 + wn * 64;

#pragma unroll
    for (int half = 0; half < 2; half++) {
        __syncwarp();
#pragma unroll
        for (int mf = 0; mf < 2; mf++)
#pragma unroll
            for (int nf = 0; nf < 2; nf++)
                wmma::store_matrix_sync(&buf[mf * 16 * 36 + nf * 16], c[mf][half * 2 + nf], 36, wmma::mem_row_major);
        __syncwarp();
        if (ok) {
#pragma unroll
            for (int j = 0; j < 32; j += 2) {
                float2 v;
                v.x = buf[lane * 36 + j]     * w;
                v.y = buf[lane * 36 + j + 1] * w;
                *(float2*)&g_y[ybase + half * 32 + j] = v;
            }
        }
    }
}

// ---------------- combine ---------------------------------------------------
__global__ void combine_kernel(float* __restrict__ out) {
    int i  = blockIdx.x * blockDim.x + threadIdx.x;
    int t  = i / (DHID / 4);
    int d4 = i % (DHID / 4);
    const float4 a = *(const float4*)&g_y[((size_t)t * 2 + 0) * DHID + d4 * 4];
    const float4 b = *(const float4*)&g_y[((size_t)t * 2 + 1) * DHID + d4 * 4];
    float4 o;
    o.x = a.x + b.x; o.y = a.y + b.y; o.z = a.z + b.z; o.w = a.w + b.w;
    *(float4*)&out[(size_t)t * DHID + d4 * 4] = o;
}

// ---------------- launch ----------------------------------------------------
extern "C" void kernel_launch(void* const* d_in, const int* in_sizes, int n_in,
                              void* d_out, int out_size) {
    const float* x  = (const float*)d_in[0];
    const float* rw = (const float*)d_in[1];
    const float* wg = (const float*)d_in[2];
    const float* wu = (const float*)d_in[3];
    const float* wd = (const float*)d_in[4];
    float* out = (float*)d_out;

    cudaFuncSetAttribute(gu_wmma_kernel,   cudaFuncAttributeMaxDynamicSharedMemorySize, GU_SMEM);
    cudaFuncSetAttribute(down_wmma_kernel, cudaFuncAttributeMaxDynamicSharedMemorySize, DW_SMEM);

    zero_counts_kernel<<<1, 32>>>();
    router_kernel<<<T_TOK / 8, 256>>>(x, rw);
    gather_x_kernel<<<dim3(T_TOK, NEXP), 128>>>(x);

    const int SPLIT_BLKS = (NEXP * DHID * FINT) / (256 * 8);   // 5632
    split_kernel<<<dim3(SPLIT_BLKS, 3), 256>>>(wg, wu, wd);

    gu_wmma_kernel  <<<dim3(FINT / 64, T_TOK / 128, NEXP), 256, GU_SMEM>>>();
    down_wmma_kernel<<<dim3(DHID / 128, T_TOK / 128, NEXP), 256, DW_SMEM>>>();

    combine_kernel<<<(T_TOK * DHID / 4) / 256, 256>>>(out);
}

// round 9
// speedup vs baseline: 2.8985x; 2.8985x over previous
#include <cuda_runtime.h>
#include <cuda_fp16.h>
#include <mma.h>
#include <math.h>
#include <stdint.h>

using namespace nvcuda;

#define T_TOK 2048
#define DHID  1024
#define FINT  1408
#define NEXP  8

// ---------------- device scratch (static: no allocations allowed) ----------
__device__ int            g_count[NEXP];
__device__ int            g_tok[NEXP * T_TOK];
__device__ float          g_wt [NEXP * T_TOK];
__device__ unsigned char  g_kslot[NEXP * T_TOK];

// gathered activations per (expert, slot), fp16, K-major rows
__device__ __half         g_x16[(size_t)NEXP * T_TOK * DHID];
// gated intermediate, fp16
__device__ __half         g_h16[(size_t)NEXP * T_TOK * FINT];
// per (token, k) down-proj output
__device__ float          g_y[(size_t)T_TOK * 2 * DHID];

// ---------------- routing ---------------------------------------------------
__global__ void zero_counts_kernel() {
    if (threadIdx.x < NEXP) g_count[threadIdx.x] = 0;
}

__global__ void router_kernel(const float* __restrict__ x,
                              const float* __restrict__ rw) {
    int warp = (blockIdx.x * blockDim.x + threadIdx.x) >> 5;
    int lane = threadIdx.x & 31;
    if (warp >= T_TOK) return;
    const float* xt = x + (size_t)warp * DHID;

    float logit[NEXP];
#pragma unroll
    for (int e = 0; e < NEXP; e++) {
        const float* w = rw + (size_t)e * DHID;
        float s = 0.f;
        for (int i = lane; i < DHID; i += 32) s += xt[i] * w[i];
#pragma unroll
        for (int o = 16; o > 0; o >>= 1) s += __shfl_xor_sync(0xffffffffu, s, o);
        logit[e] = s;
    }
    if (lane == 0) {
        float m = logit[0];
#pragma unroll
        for (int e = 1; e < NEXP; e++) m = fmaxf(m, logit[e]);
        float p[NEXP];
#pragma unroll
        for (int e = 0; e < NEXP; e++) p[e] = expf(logit[e] - m);
        int i1 = 0; float v1 = p[0];
#pragma unroll
        for (int e = 1; e < NEXP; e++) if (p[e] > v1) { v1 = p[e]; i1 = e; }
        int i2 = -1; float v2 = -1.f;
#pragma unroll
        for (int e = 0; e < NEXP; e++) {
            if (e == i1) continue;
            if (p[e] > v2) { v2 = p[e]; i2 = e; }
        }
        float inv = 1.f / (v1 + v2);
        int pos1 = atomicAdd(&g_count[i1], 1);
        g_tok[i1 * T_TOK + pos1] = warp;  g_wt[i1 * T_TOK + pos1] = v1 * inv;  g_kslot[i1 * T_TOK + pos1] = 0;
        int pos2 = atomicAdd(&g_count[i2], 1);
        g_tok[i2 * T_TOK + pos2] = warp;  g_wt[i2 * T_TOK + pos2] = v2 * inv;  g_kslot[i2 * T_TOK + pos2] = 1;
    }
}

// gather routed tokens into per-expert contiguous fp16 rows
__global__ void gather_x_kernel(const float* __restrict__ x) {
    int s = blockIdx.x, e = blockIdx.y;
    if (s >= g_count[e]) return;
    int t = g_tok[e * T_TOK + s];
    const float* src = x + (size_t)t * DHID;
    size_t dst = ((size_t)e * T_TOK + s) * DHID;
    for (int i = threadIdx.x; i < DHID; i += 128)
        g_x16[dst + i] = __float2half_rn(src[i]);
}

// ---------------- gate+up WMMA GEMM with fused SwiGLU epilogue -------------
// Block tile: 128m x 64n, two B matrices. 8 warps = 4m x 2n, warp tile 32x32.
// D = A16 * (Wh + Wl), 2 MMA passes. W split fp32->fp16 hi/lo in-loop.
__global__ void __launch_bounds__(256) gu_wmma_kernel(const float* __restrict__ wg,
                                                      const float* __restrict__ wu) {
    int e   = blockIdx.z;
    int cnt = g_count[e];
    int m0  = blockIdx.y * 128;
    if (m0 >= cnt) return;
    int n0  = blockIdx.x * 64;

    __shared__ union {
        struct {
            __half A [128][40];
            __half Bh[2][32][72];
            __half Bl[2][32][72];
        } ld;
        float ebuf[8][32 * 36];   // ldm 36: multiple of 4 floats (16B)
    } sm;

    int tid = threadIdx.x, wid = tid >> 5, lane = tid & 31;
    int wm = wid & 3, wn = wid >> 2;

    const float* W[2];
    W[0] = wg + (size_t)e * DHID * FINT + n0;
    W[1] = wu + (size_t)e * DHID * FINT + n0;
    size_t aBase = (size_t)e * T_TOK + m0;

    wmma::fragment<wmma::accumulator, 16, 16, 16, float> c[2][2][2];
#pragma unroll
    for (int mat = 0; mat < 2; mat++)
#pragma unroll
        for (int mf = 0; mf < 2; mf++)
#pragma unroll
            for (int nf = 0; nf < 2; nf++)
                wmma::fill_fragment(c[mat][mf][nf], 0.0f);

    for (int k0 = 0; k0 < DHID; k0 += 32) {
        __syncthreads();
        // A: 128 rows x 32 k fp16 = 512 uint4 -> 2 per thread
#pragma unroll
        for (int i = 0; i < 2; i++) {
            int idx = tid + i * 256;
            int r = idx >> 2, cc = idx & 3;
            *(uint4*)&sm.ld.A[r][cc * 8] =
                *(const uint4*)(g_x16 + (aBase + r) * DHID + k0 + cc * 8);
        }
        // B: 2 mats x 32 rows x 64 floats = 1024 float4 -> 4 per thread, split hi/lo
#pragma unroll
        for (int i = 0; i < 4; i++) {
            int idx = tid + i * 256;
            int mat = idx >> 9;
            int rem = idx & 511;
            int kk = rem >> 4, cc = rem & 15;
            float4 v = *(const float4*)&W[mat][(size_t)(k0 + kk) * FINT + cc * 4];
            __half hx = __float2half_rn(v.x);
            __half hy = __float2half_rn(v.y);
            __half hz = __float2half_rn(v.z);
            __half hw = __float2half_rn(v.w);
            __half2 h01; h01.x = hx; h01.y = hy;
            __half2 h23; h23.x = hz; h23.y = hw;
            __half2 l01, l23;
            l01.x = __float2half_rn(v.x - __half2float(hx));
            l01.y = __float2half_rn(v.y - __half2float(hy));
            l23.x = __float2half_rn(v.z - __half2float(hz));
            l23.y = __float2half_rn(v.w - __half2float(hw));
            *(__half2*)&sm.ld.Bh[mat][kk][cc * 4 + 0] = h01;
            *(__half2*)&sm.ld.Bh[mat][kk][cc * 4 + 2] = h23;
            *(__half2*)&sm.ld.Bl[mat][kk][cc * 4 + 0] = l01;
            *(__half2*)&sm.ld.Bl[mat][kk][cc * 4 + 2] = l23;
        }
        __syncthreads();

#pragma unroll
        for (int kk16 = 0; kk16 < 32; kk16 += 16) {
            wmma::fragment<wmma::matrix_a, 16, 16, 16, __half, wmma::row_major> a[2];
#pragma unroll
            for (int mf = 0; mf < 2; mf++)
                wmma::load_matrix_sync(a[mf], &sm.ld.A[wm * 32 + mf * 16][kk16], 40);
#pragma unroll
            for (int mat = 0; mat < 2; mat++) {
#pragma unroll
                for (int nf = 0; nf < 2; nf++) {
                    wmma::fragment<wmma::matrix_b, 16, 16, 16, __half, wmma::row_major> bh, bl;
                    wmma::load_matrix_sync(bh, &sm.ld.Bh[mat][kk16][wn * 32 + nf * 16], 72);
                    wmma::load_matrix_sync(bl, &sm.ld.Bl[mat][kk16][wn * 32 + nf * 16], 72);
#pragma unroll
                    for (int mf = 0; mf < 2; mf++) {
                        wmma::mma_sync(c[mat][mf][nf], a[mf], bh, c[mat][mf][nf]);
                        wmma::mma_sync(c[mat][mf][nf], a[mf], bl, c[mat][mf][nf]);
                    }
                }
            }
        }
    }

    // ---- fused SwiGLU epilogue ----
    __syncthreads();
    float* buf = sm.ebuf[wid];
    int grow = m0 + wm * 32 + lane;
    bool ok = grow < cnt;
    size_t hbase = ((size_t)e * T_TOK + grow) * FINT + n0 + wn * 32;

#pragma unroll
    for (int mf = 0; mf < 2; mf++)
#pragma unroll
        for (int nf = 0; nf < 2; nf++)
            wmma::store_matrix_sync(&buf[mf * 16 * 36 + nf * 16], c[0][mf][nf], 36, wmma::mem_row_major);
    __syncwarp();
    float gv[32];
#pragma unroll
    for (int j = 0; j < 32; j++) gv[j] = buf[lane * 36 + j];
    __syncwarp();
#pragma unroll
    for (int mf = 0; mf < 2; mf++)
#pragma unroll
        for (int nf = 0; nf < 2; nf++)
            wmma::store_matrix_sync(&buf[mf * 16 * 36 + nf * 16], c[1][mf][nf], 36, wmma::mem_row_major);
    __syncwarp();
    if (ok) {
#pragma unroll
        for (int j = 0; j < 32; j += 2) {
            float u0 = buf[lane * 36 + j];
            float u1 = buf[lane * 36 + j + 1];
            float g0 = gv[j], g1 = gv[j + 1];
            float h0 = g0 / (1.f + expf(-g0)) * u0;
            float h1 = g1 / (1.f + expf(-g1)) * u1;
            __half2 vh;
            vh.x = __float2half_rn(h0);
            vh.y = __float2half_rn(h1);
            *(__half2*)&g_h16[hbase + j] = vh;
        }
    }
}

// ---------------- down WMMA GEMM with routing-weight epilogue --------------
// Block tile 128m x 128n; 8 warps = 4m x 2n; warp tile 32 x 64. 2 MMA passes.
__global__ void __launch_bounds__(256) down_wmma_kernel(const float* __restrict__ wd) {
    int e   = blockIdx.z;
    int cnt = g_count[e];
    int m0  = blockIdx.y * 128;
    if (m0 >= cnt) return;
    int n0  = blockIdx.x * 128;

    __shared__ union {
        struct {
            __half A [128][40];
            __half Bh[32][136];
            __half Bl[32][136];
        } ld;
        float ebuf[8][32 * 36];
    } sm;

    int tid = threadIdx.x, wid = tid >> 5, lane = tid & 31;
    int wm = wid & 3, wn = wid >> 2;

    const float* W = wd + (size_t)e * FINT * DHID + n0;
    size_t aBase = (size_t)e * T_TOK + m0;

    wmma::fragment<wmma::accumulator, 16, 16, 16, float> c[2][4];
#pragma unroll
    for (int mf = 0; mf < 2; mf++)
#pragma unroll
        for (int nf = 0; nf < 4; nf++)
            wmma::fill_fragment(c[mf][nf], 0.0f);

    for (int k0 = 0; k0 < FINT; k0 += 32) {
        __syncthreads();
        // A: 128 rows x 32 k fp16 = 512 uint4 -> 2 per thread
#pragma unroll
        for (int i = 0; i < 2; i++) {
            int idx = tid + i * 256;
            int r = idx >> 2, cc = idx & 3;
            *(uint4*)&sm.ld.A[r][cc * 8] =
                *(const uint4*)(g_h16 + (aBase + r) * FINT + k0 + cc * 8);
        }
        // B: 32 rows x 128 floats = 1024 float4 -> 4 per thread, split hi/lo
#pragma unroll
        for (int i = 0; i < 4; i++) {
            int idx = tid + i * 256;
            int kk = idx >> 5, cc = idx & 31;
            float4 v = *(const float4*)&W[(size_t)(k0 + kk) * DHID + cc * 4];
            __half hx = __float2half_rn(v.x);
            __half hy = __float2half_rn(v.y);
            __half hz = __float2half_rn(v.z);
            __half hw = __float2half_rn(v.w);
            __half2 h01; h01.x = hx; h01.y = hy;
            __half2 h23; h23.x = hz; h23.y = hw;
            __half2 l01, l23;
            l01.x = __float2half_rn(v.x - __half2float(hx));
            l01.y = __float2half_rn(v.y - __half2float(hy));
            l23.x = __float2half_rn(v.z - __half2float(hz));
            l23.y = __float2half_rn(v.w - __half2float(hw));
            *(__half2*)&sm.ld.Bh[kk][cc * 4 + 0] = h01;
            *(__half2*)&sm.ld.Bh[kk][cc * 4 + 2] = h23;
            *(__half2*)&sm.ld.Bl[kk][cc * 4 + 0] = l01;
            *(__half2*)&sm.ld.Bl[kk][cc * 4 + 2] = l23;
        }
        __syncthreads();

#pragma unroll
        for (int kk16 = 0; kk16 < 32; kk16 += 16) {
            wmma::fragment<wmma::matrix_a, 16, 16, 16, __half, wmma::row_major> a[2];
#pragma unroll
            for (int mf = 0; mf < 2; mf++)
                wmma::load_matrix_sync(a[mf], &sm.ld.A[wm * 32 + mf * 16][kk16], 40);
#pragma unroll
            for (int nf = 0; nf < 4; nf++) {
                wmma::fragment<wmma::matrix_b, 16, 16, 16, __half, wmma::row_major> bh, bl;
                wmma::load_matrix_sync(bh, &sm.ld.Bh[kk16][wn * 64 + nf * 16], 136);
                wmma::load_matrix_sync(bl, &sm.ld.Bl[kk16][wn * 64 + nf * 16], 136);
#pragma unroll
                for (int mf = 0; mf < 2; mf++) {
                    wmma::mma_sync(c[mf][nf], a[mf], bh, c[mf][nf]);
                    wmma::mma_sync(c[mf][nf], a[mf], bl, c[mf][nf]);
                }
            }
        }
    }

    // ---- scaled scatter epilogue (two 32-col halves through smem) ----
    __syncthreads();
    float* buf = sm.ebuf[wid];
    int grow = m0 + wm * 32 + lane;
    bool ok = grow < cnt;
    int   tok = 0, ks = 0;
    float w = 0.f;
    if (ok) {
        tok = g_tok[e * T_TOK + grow];
        w   = g_wt [e * T_TOK + grow];
        ks  = g_kslot[e * T_TOK + grow];
    }
    size_t ybase = ((size_t)tok * 2 + ks) * DHID + n0 + wn * 64;

#pragma unroll
    for (int half = 0; half < 2; half++) {
        __syncwarp();
#pragma unroll
        for (int mf = 0; mf < 2; mf++)
#pragma unroll
            for (int nf = 0; nf < 2; nf++)
                wmma::store_matrix_sync(&buf[mf * 16 * 36 + nf * 16], c[mf][half * 2 + nf], 36, wmma::mem_row_major);
        __syncwarp();
        if (ok) {
#pragma unroll
            for (int j = 0; j < 32; j += 2) {
                float2 v;
                v.x = buf[lane * 36 + j]     * w;
                v.y = buf[lane * 36 + j + 1] * w;
                *(float2*)&g_y[ybase + half * 32 + j] = v;
            }
        }
    }
}

// ---------------- combine ---------------------------------------------------
__global__ void combine_kernel(float* __restrict__ out) {
    int i  = blockIdx.x * blockDim.x + threadIdx.x;
    int t  = i / (DHID / 4);
    int d4 = i % (DHID / 4);
    const float4 a = *(const float4*)&g_y[((size_t)t * 2 + 0) * DHID + d4 * 4];
    const float4 b = *(const float4*)&g_y[((size_t)t * 2 + 1) * DHID + d4 * 4];
    float4 o;
    o.x = a.x + b.x; o.y = a.y + b.y; o.z = a.z + b.z; o.w = a.w + b.w;
    *(float4*)&out[(size_t)t * DHID + d4 * 4] = o;
}

// ---------------- launch ----------------------------------------------------
extern "C" void kernel_launch(void* const* d_in, const int* in_sizes, int n_in,
                              void* d_out, int out_size) {
    const float* x  = (const float*)d_in[0];
    const float* rw = (const float*)d_in[1];
    const float* wg = (const float*)d_in[2];
    const float* wu = (const float*)d_in[3];
    const float* wd = (const float*)d_in[4];
    float* out = (float*)d_out;

    zero_counts_kernel<<<1, 32>>>();
    router_kernel<<<T_TOK / 8, 256>>>(x, rw);
    gather_x_kernel<<<dim3(T_TOK, NEXP), 128>>>(x);

    gu_wmma_kernel  <<<dim3(FINT / 64, T_TOK / 128, NEXP), 256>>>(wg, wu);
    down_wmma_kernel<<<dim3(DHID / 128, T_TOK / 128, NEXP), 256>>>(wd);

    combine_kernel<<<(T_TOK * DHID / 4) / 256, 256>>>(out);
}